// round 3
// baseline (speedup 1.0000x reference)
#include <cuda_runtime.h>
#include <math.h>

#define RBF_K 32
#define HID   64
#define NG    8
#define TPB   256
#define EV2GPA 160.21766208f

// shared memory layout in floats
#define OFF_W1T 0                       // [HID][RBF_K], w1t[j*32+k] = W1[k*64+j]
#define OFF_W2  (OFF_W1T + HID*RBF_K)   // [HID][HID] row-major (j rows)
#define OFF_B1  (OFF_W2 + HID*HID)
#define OFF_B2  (OFF_B1 + HID)
#define OFF_W3  (OFF_B2 + HID)
#define OFF_CT  (OFF_W3 + HID)
#define OFF_SE  (OFF_CT + RBF_K)        // [8] per-graph energy accum
#define OFF_SS  (OFF_SE + NG)           // [8][9] per-graph stress accum
#define OFF_DS1 (OFF_SS + NG*9 + 8)     // [HID][TPB] silu'(z1) staging (pad a bit)
#define SMEM_FLOATS (OFF_DS1 + HID*TPB)

__global__ void zero_kernel(float* __restrict__ out, int n) {
    int i = blockIdx.x * blockDim.x + threadIdx.x;
    if (i < n) out[i] = 0.0f;
}

__global__ void finalize_kernel(float* __restrict__ out, const float* __restrict__ volume, int N) {
    int i = threadIdx.x;
    if (i < NG * 9) {
        int g = i / 9;
        float vol0 = volume[g * (N / NG)];
        int idx = NG + 3 * N + i;
        out[idx] = out[idx] * (-EV2GPA / vol0);
    }
}

__device__ __forceinline__ float fsigmoid(float z) {
    return __fdividef(1.0f, 1.0f + __expf(-z));
}

__global__ __launch_bounds__(TPB, 1)
void fused_edge_kernel(const float* __restrict__ pos, const float* __restrict__ bv,
                       const int* __restrict__ src, const int* __restrict__ dst,
                       const int* __restrict__ eg,
                       const float* __restrict__ W1, const float* __restrict__ b1,
                       const float* __restrict__ W2, const float* __restrict__ b2,
                       const float* __restrict__ W3, const float* __restrict__ b3,
                       const float* __restrict__ centers,
                       float* __restrict__ out, int E, int N)
{
    extern __shared__ float sm[];
    const int tid = threadIdx.x;

    // ---- load weights into shared memory (W1 transposed so inner-k is contiguous) ----
    for (int i = tid; i < RBF_K * HID; i += TPB) {
        int k = i / HID, j = i % HID;
        sm[OFF_W1T + j * RBF_K + k] = W1[i];
    }
    for (int i = tid; i < HID * HID; i += TPB) sm[OFF_W2 + i] = W2[i];
    if (tid < HID) {
        sm[OFF_B1 + tid] = b1[tid];
        sm[OFF_B2 + tid] = b2[tid];
        sm[OFF_W3 + tid] = W3[tid];
    }
    if (tid < RBF_K)   sm[OFF_CT + tid] = centers[tid];
    if (tid < NG)      sm[OFF_SE + tid] = 0.0f;
    if (tid < NG * 9)  sm[OFF_SS + tid] = 0.0f;
    __syncthreads();

    const float b3v = b3[0];
    float* __restrict__ ds1 = &sm[OFF_DS1];

    const int stride = gridDim.x * TPB;
    for (int e = blockIdx.x * TPB + tid; e < E; e += stride) {
        const int ns = src[e], nd = dst[e];
        const int g  = eg[e];
        const float bx = bv[3 * e + 0], by = bv[3 * e + 1], bz = bv[3 * e + 2];
        const float dx = bx + pos[3 * nd + 0] - pos[3 * ns + 0];
        const float dy = by + pos[3 * nd + 1] - pos[3 * ns + 1];
        const float dz = bz + pos[3 * nd + 2] - pos[3 * ns + 2];
        const float dist = sqrtf(dx * dx + dy * dy + dz * dz + 1e-12f);

        // ---- RBF expansion (kept in registers; reused in backward) ----
        float rbf[RBF_K];
        {
            const float4* ct4 = reinterpret_cast<const float4*>(&sm[OFF_CT]);
            #pragma unroll
            for (int k4 = 0; k4 < RBF_K / 4; k4++) {
                float4 c = ct4[k4];
                float t0 = dist - c.x, t1 = dist - c.y, t2 = dist - c.z, t3 = dist - c.w;
                rbf[4 * k4 + 0] = __expf(-t0 * t0);
                rbf[4 * k4 + 1] = __expf(-t1 * t1);
                rbf[4 * k4 + 2] = __expf(-t2 * t2);
                rbf[4 * k4 + 3] = __expf(-t3 * t3);
            }
        }

        // ---- fused forward: layer1 streamed into layer2 accumulator ----
        float z2[HID];
        {
            const float4* b2v4 = reinterpret_cast<const float4*>(&sm[OFF_B2]);
            #pragma unroll
            for (int m4 = 0; m4 < HID / 4; m4++) {
                float4 b = b2v4[m4];
                z2[4 * m4 + 0] = b.x; z2[4 * m4 + 1] = b.y;
                z2[4 * m4 + 2] = b.z; z2[4 * m4 + 3] = b.w;
            }
        }

        #pragma unroll 1
        for (int j = 0; j < HID; j++) {
            float z1 = sm[OFF_B1 + j];
            const float4* w1t4 = reinterpret_cast<const float4*>(&sm[OFF_W1T + j * RBF_K]);
            #pragma unroll
            for (int k4 = 0; k4 < RBF_K / 4; k4++) {
                float4 w = w1t4[k4];
                z1 += rbf[4 * k4 + 0] * w.x + rbf[4 * k4 + 1] * w.y
                    + rbf[4 * k4 + 2] * w.z + rbf[4 * k4 + 3] * w.w;
            }
            const float sg = fsigmoid(z1);
            const float h  = z1 * sg;
            ds1[j * TPB + tid] = sg * (1.0f + z1 * (1.0f - sg));   // silu'(z1)
            const float4* w2r4 = reinterpret_cast<const float4*>(&sm[OFF_W2 + j * HID]);
            #pragma unroll
            for (int m4 = 0; m4 < HID / 4; m4++) {
                float4 w = w2r4[m4];
                z2[4 * m4 + 0] += h * w.x; z2[4 * m4 + 1] += h * w.y;
                z2[4 * m4 + 2] += h * w.z; z2[4 * m4 + 3] += h * w.w;
            }
        }

        // ---- output layer + dz2 computed in place (upstream grad = 1) ----
        float e_edge = b3v;
        #pragma unroll
        for (int m = 0; m < HID; m++) {
            const float z   = z2[m];
            const float sg  = fsigmoid(z);
            const float w3m = sm[OFF_W3 + m];
            e_edge += z * sg * w3m;
            z2[m] = w3m * (sg * (1.0f + z * (1.0f - sg)));   // dz2[m]
        }

        // ---- backward through layers: dh1 scalar per j, drbf accumulated ----
        float drbf[RBF_K];
        #pragma unroll
        for (int k = 0; k < RBF_K; k++) drbf[k] = 0.0f;

        #pragma unroll 1
        for (int j = 0; j < HID; j++) {
            float dh = 0.0f;
            const float4* w2r4 = reinterpret_cast<const float4*>(&sm[OFF_W2 + j * HID]);
            #pragma unroll
            for (int m4 = 0; m4 < HID / 4; m4++) {
                float4 w = w2r4[m4];
                dh += z2[4 * m4 + 0] * w.x + z2[4 * m4 + 1] * w.y
                    + z2[4 * m4 + 2] * w.z + z2[4 * m4 + 3] * w.w;
            }
            const float dz1 = dh * ds1[j * TPB + tid];
            const float4* w1t4 = reinterpret_cast<const float4*>(&sm[OFF_W1T + j * RBF_K]);
            #pragma unroll
            for (int k4 = 0; k4 < RBF_K / 4; k4++) {
                float4 w = w1t4[k4];
                drbf[4 * k4 + 0] += dz1 * w.x; drbf[4 * k4 + 1] += dz1 * w.y;
                drbf[4 * k4 + 2] += dz1 * w.z; drbf[4 * k4 + 3] += dz1 * w.w;
            }
        }

        // ---- d(energy)/d(dist):  dd = sum_k drbf[k] * (-2 (dist-c_k)) * rbf[k] ----
        float dd = 0.0f;
        {
            const float4* ct4 = reinterpret_cast<const float4*>(&sm[OFF_CT]);
            #pragma unroll
            for (int k4 = 0; k4 < RBF_K / 4; k4++) {
                float4 c = ct4[k4];
                dd += (drbf[4 * k4 + 0] * rbf[4 * k4 + 0]) * (dist - c.x)
                    + (drbf[4 * k4 + 1] * rbf[4 * k4 + 1]) * (dist - c.y)
                    + (drbf[4 * k4 + 2] * rbf[4 * k4 + 2]) * (dist - c.z)
                    + (drbf[4 * k4 + 3] * rbf[4 * k4 + 3]) * (dist - c.w);
            }
            dd *= -2.0f;
        }
        const float sc = __fdividef(dd, dist);
        const float gx = sc * dx, gy = sc * dy, gz = sc * dz;   // ddisp = grad wrt bond_vec

        // forces = -gpos:  gpos[dst] += ddisp, gpos[src] -= ddisp
        atomicAdd(&out[NG + 3 * nd + 0], -gx);
        atomicAdd(&out[NG + 3 * nd + 1], -gy);
        atomicAdd(&out[NG + 3 * nd + 2], -gz);
        atomicAdd(&out[NG + 3 * ns + 0],  gx);
        atomicAdd(&out[NG + 3 * ns + 1],  gy);
        atomicAdd(&out[NG + 3 * ns + 2],  gz);

        // stress raw accumulation: S += bond_vec (outer) f_ij, f_ij = -ddisp
        const float fx = -gx, fy = -gy, fz = -gz;
        float* ss = &sm[OFF_SS + g * 9];
        atomicAdd(&ss[0], bx * fx); atomicAdd(&ss[1], bx * fy); atomicAdd(&ss[2], bx * fz);
        atomicAdd(&ss[3], by * fx); atomicAdd(&ss[4], by * fy); atomicAdd(&ss[5], by * fz);
        atomicAdd(&ss[6], bz * fx); atomicAdd(&ss[7], bz * fy); atomicAdd(&ss[8], bz * fz);
        atomicAdd(&sm[OFF_SE + g], e_edge);
    }

    __syncthreads();
    if (tid < NG)     atomicAdd(&out[tid], sm[OFF_SE + tid]);
    if (tid < NG * 9) atomicAdd(&out[NG + 3 * N + tid], sm[OFF_SS + tid]);
}

extern "C" void kernel_launch(void* const* d_in, const int* in_sizes, int n_in,
                              void* d_out, int out_size) {
    const float* pos     = (const float*)d_in[0];
    const float* bv      = (const float*)d_in[1];
    const int*   src     = (const int*)  d_in[2];
    const int*   dst     = (const int*)  d_in[3];
    const int*   eg      = (const int*)  d_in[4];
    const float* volume  = (const float*)d_in[5];
    const float* centers = (const float*)d_in[6];
    const float* W1      = (const float*)d_in[7];
    const float* b1      = (const float*)d_in[8];
    const float* W2      = (const float*)d_in[9];
    const float* b2      = (const float*)d_in[10];
    const float* W3      = (const float*)d_in[11];
    const float* b3      = (const float*)d_in[12];
    float* out = (float*)d_out;

    const int N = in_sizes[0] / 3;
    const int E = in_sizes[1] / 3;

    // zero the whole output (energies, forces, stress, hessian) — it is poisoned
    zero_kernel<<<(out_size + 255) / 256, 256>>>(out, out_size);

    constexpr size_t smem_bytes = (size_t)SMEM_FLOATS * sizeof(float);
    cudaFuncSetAttribute(fused_edge_kernel,
                         cudaFuncAttributeMaxDynamicSharedMemorySize, (int)smem_bytes);

    // 296 blocks = 2 waves at 1 block/SM (high register + smem usage)
    fused_edge_kernel<<<296, TPB, smem_bytes>>>(pos, bv, src, dst, eg,
                                                W1, b1, W2, b2, W3, b3, centers,
                                                out, E, N);

    finalize_kernel<<<1, 128>>>(out, volume, N);
}

// round 4
// speedup vs baseline: 1.0474x; 1.0474x over previous
#include <cuda_runtime.h>
#include <math.h>

#define RBF_K 32
#define HID   64
#define NG    8
#define TPB   256
#define EV2GPA 160.21766208f

typedef unsigned long long ull;

// shared memory layout in floats (all offsets 16B-aligned)
#define OFF_W1T 0                       // [HID][RBF_K], w1t[j*32+k] = W1[k*64+j]
#define OFF_W2  (OFF_W1T + HID*RBF_K)   // [HID][HID] row-major (j rows)
#define OFF_B1  (OFF_W2 + HID*HID)
#define OFF_B2  (OFF_B1 + HID)
#define OFF_W3  (OFF_B2 + HID)
#define OFF_CT  (OFF_W3 + HID)
#define OFF_SE  (OFF_CT + RBF_K)        // [8] per-graph energy accum
#define OFF_SS  (OFF_SE + NG)           // [8][9] per-graph stress accum
#define OFF_DS1 (OFF_SS + NG*9 + 8)     // [HID][TPB] silu'(z1) staging
#define SMEM_FLOATS (OFF_DS1 + HID*TPB)

__device__ __forceinline__ ull pack2(float lo, float hi) {
    ull r; asm("mov.b64 %0, {%1, %2};" : "=l"(r) : "f"(lo), "f"(hi)); return r;
}
__device__ __forceinline__ void unpack2(ull v, float& lo, float& hi) {
    asm("mov.b64 {%0, %1}, %2;" : "=f"(lo), "=f"(hi) : "l"(v));
}
// packed dual fp32 fma: d = a*b + c  (elementwise on 2 packed floats, .rn — bit-identical to FFMA)
__device__ __forceinline__ ull fma2(ull a, ull b, ull c) {
    ull d; asm("fma.rn.f32x2 %0, %1, %2, %3;" : "=l"(d) : "l"(a), "l"(b), "l"(c)); return d;
}

__global__ void zero_kernel(float* __restrict__ out, int n) {
    int i = blockIdx.x * blockDim.x + threadIdx.x;
    if (i < n) out[i] = 0.0f;
}

__global__ void finalize_kernel(float* __restrict__ out, const float* __restrict__ volume, int N) {
    int i = threadIdx.x;
    if (i < NG * 9) {
        int g = i / 9;
        float vol0 = volume[g * (N / NG)];
        int idx = NG + 3 * N + i;
        out[idx] = out[idx] * (-EV2GPA / vol0);
    }
}

__device__ __forceinline__ float fsigmoid(float z) {
    return __fdividef(1.0f, 1.0f + __expf(-z));
}

__global__ __launch_bounds__(TPB, 1)
void fused_edge_kernel(const float* __restrict__ pos, const float* __restrict__ bv,
                       const int* __restrict__ src, const int* __restrict__ dst,
                       const int* __restrict__ eg,
                       const float* __restrict__ W1, const float* __restrict__ b1,
                       const float* __restrict__ W2, const float* __restrict__ b2,
                       const float* __restrict__ W3, const float* __restrict__ b3,
                       const float* __restrict__ centers,
                       float* __restrict__ out, int E, int N)
{
    extern __shared__ float sm[];
    const int tid = threadIdx.x;

    // ---- load weights into shared memory (W1 transposed so inner-k is contiguous) ----
    for (int i = tid; i < RBF_K * HID; i += TPB) {
        int k = i / HID, j = i % HID;
        sm[OFF_W1T + j * RBF_K + k] = W1[i];
    }
    for (int i = tid; i < HID * HID; i += TPB) sm[OFF_W2 + i] = W2[i];
    if (tid < HID) {
        sm[OFF_B1 + tid] = b1[tid];
        sm[OFF_B2 + tid] = b2[tid];
        sm[OFF_W3 + tid] = W3[tid];
    }
    if (tid < RBF_K)   sm[OFF_CT + tid] = centers[tid];
    if (tid < NG)      sm[OFF_SE + tid] = 0.0f;
    if (tid < NG * 9)  sm[OFF_SS + tid] = 0.0f;
    __syncthreads();

    const float b3v = b3[0];
    float* __restrict__ ds1 = &sm[OFF_DS1];

    const int stride = gridDim.x * TPB;
    for (int e = blockIdx.x * TPB + tid; e < E; e += stride) {
        const int ns = src[e], nd = dst[e];
        const int g  = eg[e];
        const float bx = bv[3 * e + 0], by = bv[3 * e + 1], bz = bv[3 * e + 2];
        const float dx = bx + pos[3 * nd + 0] - pos[3 * ns + 0];
        const float dy = by + pos[3 * nd + 1] - pos[3 * ns + 1];
        const float dz = bz + pos[3 * nd + 2] - pos[3 * ns + 2];
        const float dist = sqrtf(dx * dx + dy * dy + dz * dz + 1e-12f);

        // ---- RBF expansion, stored packed (pair i = rbf[2i], rbf[2i+1]) ----
        ull rbfp[RBF_K / 2];
        {
            const float4* ct4 = reinterpret_cast<const float4*>(&sm[OFF_CT]);
            #pragma unroll
            for (int k4 = 0; k4 < RBF_K / 4; k4++) {
                float4 c = ct4[k4];
                float t0 = dist - c.x, t1 = dist - c.y, t2 = dist - c.z, t3 = dist - c.w;
                rbfp[2 * k4 + 0] = pack2(__expf(-t0 * t0), __expf(-t1 * t1));
                rbfp[2 * k4 + 1] = pack2(__expf(-t2 * t2), __expf(-t3 * t3));
            }
        }

        // ---- fused forward: layer1 streamed into packed layer2 accumulators ----
        ull z2p[HID / 2];
        {
            const ulonglong2* b2p = reinterpret_cast<const ulonglong2*>(&sm[OFF_B2]);
            #pragma unroll
            for (int i = 0; i < HID / 4; i++) {
                ulonglong2 b = b2p[i];
                z2p[2 * i + 0] = b.x;
                z2p[2 * i + 1] = b.y;
            }
        }

        #pragma unroll 1
        for (int j = 0; j < HID; j++) {
            // z1 = b1[j] + <rbf, W1T[j,:]>   (packed, 2 accumulators)
            const ulonglong2* w1p = reinterpret_cast<const ulonglong2*>(&sm[OFF_W1T + j * RBF_K]);
            ull a0 = pack2(sm[OFF_B1 + j], 0.0f);
            ull a1 = 0ULL;
            #pragma unroll
            for (int i = 0; i < RBF_K / 4; i++) {
                ulonglong2 w = w1p[i];
                a0 = fma2(rbfp[2 * i + 0], w.x, a0);
                a1 = fma2(rbfp[2 * i + 1], w.y, a1);
            }
            float s0, s1, s2, s3;
            unpack2(a0, s0, s1); unpack2(a1, s2, s3);
            const float z1 = (s0 + s2) + (s1 + s3);

            const float sg = fsigmoid(z1);
            const float h  = z1 * sg;
            ds1[j * TPB + tid] = sg * (1.0f + z1 * (1.0f - sg));   // silu'(z1)

            const ull h2 = pack2(h, h);
            const ulonglong2* w2p = reinterpret_cast<const ulonglong2*>(&sm[OFF_W2 + j * HID]);
            #pragma unroll
            for (int i = 0; i < HID / 4; i++) {
                ulonglong2 w = w2p[i];
                z2p[2 * i + 0] = fma2(h2, w.x, z2p[2 * i + 0]);
                z2p[2 * i + 1] = fma2(h2, w.y, z2p[2 * i + 1]);
            }
        }

        // ---- output layer + dz2 computed in place (upstream grad = 1) ----
        float e_edge = b3v;
        #pragma unroll
        for (int p = 0; p < HID / 2; p++) {
            float zl, zh;
            unpack2(z2p[p], zl, zh);
            const float sgl = fsigmoid(zl), sgh = fsigmoid(zh);
            const float w3l = sm[OFF_W3 + 2 * p], w3h = sm[OFF_W3 + 2 * p + 1];
            e_edge += zl * sgl * w3l + zh * sgh * w3h;
            z2p[p] = pack2(w3l * (sgl * (1.0f + zl * (1.0f - sgl))),
                           w3h * (sgh * (1.0f + zh * (1.0f - sgh))));   // dz2 pair
        }

        // ---- backward: dh scalar per j, drbf packed accumulate ----
        ull drbfp[RBF_K / 2];
        #pragma unroll
        for (int i = 0; i < RBF_K / 2; i++) drbfp[i] = 0ULL;

        #pragma unroll 1
        for (int j = 0; j < HID; j++) {
            const ulonglong2* w2p = reinterpret_cast<const ulonglong2*>(&sm[OFF_W2 + j * HID]);
            ull a0 = 0ULL, a1 = 0ULL;
            #pragma unroll
            for (int i = 0; i < HID / 4; i++) {
                ulonglong2 w = w2p[i];
                a0 = fma2(z2p[2 * i + 0], w.x, a0);
                a1 = fma2(z2p[2 * i + 1], w.y, a1);
            }
            float s0, s1, s2, s3;
            unpack2(a0, s0, s1); unpack2(a1, s2, s3);
            const float dh = (s0 + s2) + (s1 + s3);

            const float dz1 = dh * ds1[j * TPB + tid];
            const ull dz1p = pack2(dz1, dz1);
            const ulonglong2* w1p = reinterpret_cast<const ulonglong2*>(&sm[OFF_W1T + j * RBF_K]);
            #pragma unroll
            for (int i = 0; i < RBF_K / 4; i++) {
                ulonglong2 w = w1p[i];
                drbfp[2 * i + 0] = fma2(dz1p, w.x, drbfp[2 * i + 0]);
                drbfp[2 * i + 1] = fma2(dz1p, w.y, drbfp[2 * i + 1]);
            }
        }

        // ---- d(energy)/d(dist):  dd = -2 * sum_k drbf[k]*rbf[k]*(dist - c_k) ----
        float dd = 0.0f;
        #pragma unroll
        for (int i = 0; i < RBF_K / 2; i++) {
            float r0, r1, g0, g1;
            unpack2(rbfp[i], r0, r1);
            unpack2(drbfp[i], g0, g1);
            const float c0 = sm[OFF_CT + 2 * i], c1 = sm[OFF_CT + 2 * i + 1];
            dd += (g0 * r0) * (dist - c0) + (g1 * r1) * (dist - c1);
        }
        dd *= -2.0f;

        const float sc = __fdividef(dd, dist);
        const float gx = sc * dx, gy = sc * dy, gz = sc * dz;   // grad wrt bond_vec / disp

        // forces = -gpos:  gpos[dst] += ddisp, gpos[src] -= ddisp
        atomicAdd(&out[NG + 3 * nd + 0], -gx);
        atomicAdd(&out[NG + 3 * nd + 1], -gy);
        atomicAdd(&out[NG + 3 * nd + 2], -gz);
        atomicAdd(&out[NG + 3 * ns + 0],  gx);
        atomicAdd(&out[NG + 3 * ns + 1],  gy);
        atomicAdd(&out[NG + 3 * ns + 2],  gz);

        // stress raw accumulation: S += bond_vec (outer) f_ij, f_ij = -ddisp
        const float fx = -gx, fy = -gy, fz = -gz;
        float* ss = &sm[OFF_SS + g * 9];
        atomicAdd(&ss[0], bx * fx); atomicAdd(&ss[1], bx * fy); atomicAdd(&ss[2], bx * fz);
        atomicAdd(&ss[3], by * fx); atomicAdd(&ss[4], by * fy); atomicAdd(&ss[5], by * fz);
        atomicAdd(&ss[6], bz * fx); atomicAdd(&ss[7], bz * fy); atomicAdd(&ss[8], bz * fz);
        atomicAdd(&sm[OFF_SE + g], e_edge);
    }

    __syncthreads();
    if (tid < NG)     atomicAdd(&out[tid], sm[OFF_SE + tid]);
    if (tid < NG * 9) atomicAdd(&out[NG + 3 * N + tid], sm[OFF_SS + tid]);
}

extern "C" void kernel_launch(void* const* d_in, const int* in_sizes, int n_in,
                              void* d_out, int out_size) {
    const float* pos     = (const float*)d_in[0];
    const float* bv      = (const float*)d_in[1];
    const int*   src     = (const int*)  d_in[2];
    const int*   dst     = (const int*)  d_in[3];
    const int*   eg      = (const int*)  d_in[4];
    const float* volume  = (const float*)d_in[5];
    const float* centers = (const float*)d_in[6];
    const float* W1      = (const float*)d_in[7];
    const float* b1      = (const float*)d_in[8];
    const float* W2      = (const float*)d_in[9];
    const float* b2      = (const float*)d_in[10];
    const float* W3      = (const float*)d_in[11];
    const float* b3      = (const float*)d_in[12];
    float* out = (float*)d_out;

    const int N = in_sizes[0] / 3;
    const int E = in_sizes[1] / 3;

    // zero the whole output (energies, forces, stress, hessian) — it is poisoned
    zero_kernel<<<(out_size + 255) / 256, 256>>>(out, out_size);

    constexpr size_t smem_bytes = (size_t)SMEM_FLOATS * sizeof(float);
    cudaFuncSetAttribute(fused_edge_kernel,
                         cudaFuncAttributeMaxDynamicSharedMemorySize, (int)smem_bytes);

    fused_edge_kernel<<<296, TPB, smem_bytes>>>(pos, bv, src, dst, eg,
                                                W1, b1, W2, b2, W3, b3, centers,
                                                out, E, N);

    finalize_kernel<<<1, 128>>>(out, volume, N);
}

// round 6
// speedup vs baseline: 1.1234x; 1.0725x over previous
#include <cuda_runtime.h>
#include <cuda_fp16.h>
#include <math.h>

#define RBF_K 32
#define HID   64
#define NG    8
#define TPB   256
#define NMAX  49152
#define EV2GPA 160.21766208f

typedef unsigned long long ull;

// ---- shared memory layout (float indices) ----
#define OFF_W1T 0                        // [HID][RBF_K] transposed W1
#define OFF_W2  (OFF_W1T + HID*RBF_K)    // [HID][HID]
#define OFF_B1  (OFF_W2 + HID*HID)
#define OFF_B2  (OFF_B1 + HID)
#define OFF_W3  (OFF_B2 + HID)
#define OFF_CT  (OFF_W3 + HID)
#define OFF_SE  (OFF_CT + RBF_K)         // [8]
#define OFF_SS  (OFF_SE + NG)            // [72]
#define OFF_H   (OFF_SS + NG*9)          // ull[HID][TPB]  (h pairs, fp32x2) — 8B aligned (even float idx)
#define OFF_T   (OFF_H + HID*TPB*2)      // half2[HID][TPB] (t pairs)
#define SMEM_FLOATS (OFF_T + HID*TPB)

// scratch: [0:8) energy, [8:8+3N) gpos accum, [8+3N:+72) raw stress
__device__ float g_scr[8 + 3 * NMAX + 72];

__device__ __forceinline__ ull pack2(float lo, float hi) {
    ull r; asm("mov.b64 %0, {%1, %2};" : "=l"(r) : "f"(lo), "f"(hi)); return r;
}
__device__ __forceinline__ void unpack2(ull v, float& lo, float& hi) {
    asm("mov.b64 {%0, %1}, %2;" : "=f"(lo), "=f"(hi) : "l"(v));
}
__device__ __forceinline__ ull fma2(ull a, ull b, ull c) {
    ull d; asm("fma.rn.f32x2 %0, %1, %2, %3;" : "=l"(d) : "l"(a), "l"(b), "l"(c)); return d;
}
__device__ __forceinline__ float red4(ull a0, ull a1) {
    float x0, x1, x2, x3;
    unpack2(a0, x0, x1); unpack2(a1, x2, x3);
    return (x0 + x2) + (x1 + x3);
}
__device__ __forceinline__ float fsigmoid(float z) {
    return __fdividef(1.0f, 1.0f + __expf(-z));
}

__global__ __launch_bounds__(TPB, 1)
void fused_edge_kernel(const float* __restrict__ pos, const float* __restrict__ bv,
                       const int* __restrict__ src, const int* __restrict__ dst,
                       const int* __restrict__ eg,
                       const float* __restrict__ W1, const float* __restrict__ b1,
                       const float* __restrict__ W2, const float* __restrict__ b2,
                       const float* __restrict__ W3, const float* __restrict__ b3,
                       const float* __restrict__ centers,
                       int E, int N)
{
    extern __shared__ float sm[];
    const int tid = threadIdx.x;

    for (int i = tid; i < RBF_K * HID; i += TPB) {
        int k = i / HID, j = i % HID;
        sm[OFF_W1T + j * RBF_K + k] = W1[i];     // transpose
    }
    for (int i = tid; i < HID * HID; i += TPB) sm[OFF_W2 + i] = W2[i];
    if (tid < HID) {
        sm[OFF_B1 + tid] = b1[tid];
        sm[OFF_B2 + tid] = b2[tid];
        sm[OFF_W3 + tid] = W3[tid];
    }
    if (tid < RBF_K)  sm[OFF_CT + tid] = centers[tid];
    if (tid < NG)     sm[OFF_SE + tid] = 0.0f;
    if (tid < NG * 9) sm[OFF_SS + tid] = 0.0f;
    __syncthreads();

    const float b3v = b3[0];
    ull*    __restrict__ hbuf = reinterpret_cast<ull*>(&sm[OFF_H]);
    __half2* __restrict__ tbuf = reinterpret_cast<__half2*>(&sm[OFF_T]);
    const float4* ct4 = reinterpret_cast<const float4*>(&sm[OFF_CT]);

    const int P = gridDim.x * TPB;
    for (int eA = blockIdx.x * TPB + tid; eA < E; eA += 2 * P) {
        const int eB0 = eA + P;
        const float vB = (eB0 < E) ? 1.0f : 0.0f;
        const int eB = (eB0 < E) ? eB0 : eA;

        const int nsA = src[eA], ndA = dst[eA], gA = eg[eA];
        const int nsB = src[eB], ndB = dst[eB], gB = eg[eB];
        const float bxA = bv[3*eA+0], byA = bv[3*eA+1], bzA = bv[3*eA+2];
        const float bxB = bv[3*eB+0], byB = bv[3*eB+1], bzB = bv[3*eB+2];
        const float dxA = bxA + pos[3*ndA+0] - pos[3*nsA+0];
        const float dyA = byA + pos[3*ndA+1] - pos[3*nsA+1];
        const float dzA = bzA + pos[3*ndA+2] - pos[3*nsA+2];
        const float dxB = bxB + pos[3*ndB+0] - pos[3*nsB+0];
        const float dyB = byB + pos[3*ndB+1] - pos[3*nsB+1];
        const float dzB = bzB + pos[3*ndB+2] - pos[3*nsB+2];
        const float distA = sqrtf(dxA*dxA + dyA*dyA + dzA*dzA + 1e-12f);
        const float distB = sqrtf(dxB*dxB + dyB*dyB + dzB*dzB + 1e-12f);

        // ---- P0: rbf and rbf' = -2(d-c)rbf, packed, both edges ----
        ull rA[RBF_K/2], dA[RBF_K/2], rB[RBF_K/2], dB[RBF_K/2];
        #pragma unroll
        for (int k4 = 0; k4 < RBF_K / 4; k4++) {
            float4 c = ct4[k4];
            {
                float t0 = distA-c.x, t1 = distA-c.y, t2 = distA-c.z, t3 = distA-c.w;
                float r0 = __expf(-t0*t0), r1 = __expf(-t1*t1), r2 = __expf(-t2*t2), r3 = __expf(-t3*t3);
                rA[2*k4+0] = pack2(r0, r1);          rA[2*k4+1] = pack2(r2, r3);
                dA[2*k4+0] = pack2(-2.f*t0*r0, -2.f*t1*r1);
                dA[2*k4+1] = pack2(-2.f*t2*r2, -2.f*t3*r3);
            }
            {
                float t0 = distB-c.x, t1 = distB-c.y, t2 = distB-c.z, t3 = distB-c.w;
                float r0 = __expf(-t0*t0), r1 = __expf(-t1*t1), r2 = __expf(-t2*t2), r3 = __expf(-t3*t3);
                rB[2*k4+0] = pack2(r0, r1);          rB[2*k4+1] = pack2(r2, r3);
                dB[2*k4+0] = pack2(-2.f*t0*r0, -2.f*t1*r1);
                dB[2*k4+1] = pack2(-2.f*t2*r2, -2.f*t3*r3);
            }
        }

        // ---- P1: layer1 for all j, both edges; stage h (fp32 pair) and t (fp16 pair) ----
        #pragma unroll 1
        for (int j = 0; j < HID; j++) {
            const ulonglong2* w1p = reinterpret_cast<const ulonglong2*>(&sm[OFF_W1T + j * RBF_K]);
            ull zA0 = 0, zA1 = 0, uA0 = 0, uA1 = 0;
            ull zB0 = 0, zB1 = 0, uB0 = 0, uB1 = 0;
            #pragma unroll
            for (int i = 0; i < RBF_K / 4; i++) {
                ulonglong2 w = w1p[i];
                zA0 = fma2(rA[2*i+0], w.x, zA0);  zA1 = fma2(rA[2*i+1], w.y, zA1);
                uA0 = fma2(dA[2*i+0], w.x, uA0);  uA1 = fma2(dA[2*i+1], w.y, uA1);
                zB0 = fma2(rB[2*i+0], w.x, zB0);  zB1 = fma2(rB[2*i+1], w.y, zB1);
                uB0 = fma2(dB[2*i+0], w.x, uB0);  uB1 = fma2(dB[2*i+1], w.y, uB1);
            }
            const float b1j = sm[OFF_B1 + j];
            const float z1A = red4(zA0, zA1) + b1j;
            const float z1B = red4(zB0, zB1) + b1j;
            const float uA  = red4(uA0, uA1);
            const float uB  = red4(uB0, uB1);
            const float sgA = fsigmoid(z1A), sgB = fsigmoid(z1B);
            const float hA = z1A * sgA, hB = z1B * sgB;
            const float tA = (sgA * (1.0f + z1A * (1.0f - sgA))) * uA;  // silu'(z1)*u
            const float tB = (sgB * (1.0f + z1B * (1.0f - sgB))) * uB;
            hbuf[j * TPB + tid] = pack2(hA, hB);
            tbuf[j * TPB + tid] = __floats2half2_rn(tA, tB);
        }

        // ---- P2: z2 accumulation, shared w2 row loads ----
        ull z2A[HID/2], z2B[HID/2];
        {
            const ulonglong2* b2p = reinterpret_cast<const ulonglong2*>(&sm[OFF_B2]);
            #pragma unroll
            for (int i = 0; i < HID / 4; i++) {
                ulonglong2 b = b2p[i];
                z2A[2*i+0] = b.x; z2A[2*i+1] = b.y;
                z2B[2*i+0] = b.x; z2B[2*i+1] = b.y;
            }
        }
        #pragma unroll 1
        for (int j = 0; j < HID; j++) {
            float hA, hB;
            unpack2(hbuf[j * TPB + tid], hA, hB);
            const ull h2A = pack2(hA, hA), h2B = pack2(hB, hB);
            const ulonglong2* w2p = reinterpret_cast<const ulonglong2*>(&sm[OFF_W2 + j * HID]);
            #pragma unroll
            for (int i = 0; i < HID / 4; i++) {
                ulonglong2 w = w2p[i];
                z2A[2*i+0] = fma2(h2A, w.x, z2A[2*i+0]);
                z2A[2*i+1] = fma2(h2A, w.y, z2A[2*i+1]);
                z2B[2*i+0] = fma2(h2B, w.x, z2B[2*i+0]);
                z2B[2*i+1] = fma2(h2B, w.y, z2B[2*i+1]);
            }
        }

        // ---- P3: output layer; dz2 in place (upstream grad = 1) ----
        float eEA = b3v, eEB = b3v;
        {
            const float2* w3f = reinterpret_cast<const float2*>(&sm[OFF_W3]);
            #pragma unroll
            for (int p = 0; p < HID / 2; p++) {
                float2 w3 = w3f[p];
                float zl, zh;
                unpack2(z2A[p], zl, zh);
                float sgl = fsigmoid(zl), sgh = fsigmoid(zh);
                eEA += zl * sgl * w3.x + zh * sgh * w3.y;
                z2A[p] = pack2(w3.x * (sgl * (1.0f + zl * (1.0f - sgl))),
                               w3.y * (sgh * (1.0f + zh * (1.0f - sgh))));
                unpack2(z2B[p], zl, zh);
                sgl = fsigmoid(zl); sgh = fsigmoid(zh);
                eEB += zl * sgl * w3.x + zh * sgh * w3.y;
                z2B[p] = pack2(w3.x * (sgl * (1.0f + zl * (1.0f - sgl))),
                               w3.y * (sgh * (1.0f + zh * (1.0f - sgh))));
            }
        }

        // ---- P4: dh per j (shared w2 loads), dd = sum_j dh_j * t_j ----
        float ddA = 0.0f, ddB = 0.0f;
        #pragma unroll 1
        for (int j = 0; j < HID; j++) {
            const ulonglong2* w2p = reinterpret_cast<const ulonglong2*>(&sm[OFF_W2 + j * HID]);
            ull a0 = 0, a1 = 0, c0 = 0, c1 = 0;
            #pragma unroll
            for (int i = 0; i < HID / 4; i++) {
                ulonglong2 w = w2p[i];
                a0 = fma2(z2A[2*i+0], w.x, a0);  a1 = fma2(z2A[2*i+1], w.y, a1);
                c0 = fma2(z2B[2*i+0], w.x, c0);  c1 = fma2(z2B[2*i+1], w.y, c1);
            }
            const float dhA = red4(a0, a1);
            const float dhB = red4(c0, c1);
            const float2 t = __half22float2(tbuf[j * TPB + tid]);
            ddA += dhA * t.x;
            ddB += dhB * t.y;
        }

        // ---- epilogue ----
        ddB *= vB;
        const float eB_energy = eEB * vB;
        const float scA = __fdividef(ddA, distA);
        const float scB = __fdividef(ddB, distB);
        const float gxA = scA * dxA, gyA = scA * dyA, gzA = scA * dzA;
        const float gxB = scB * dxB, gyB = scB * dyB, gzB = scB * dzB;

        // gpos accumulation into scratch (forces = -gpos applied in finalize)
        atomicAdd(&g_scr[8 + 3*ndA + 0], gxA);
        atomicAdd(&g_scr[8 + 3*ndA + 1], gyA);
        atomicAdd(&g_scr[8 + 3*ndA + 2], gzA);
        atomicAdd(&g_scr[8 + 3*nsA + 0], -gxA);
        atomicAdd(&g_scr[8 + 3*nsA + 1], -gyA);
        atomicAdd(&g_scr[8 + 3*nsA + 2], -gzA);
        atomicAdd(&g_scr[8 + 3*ndB + 0], gxB);
        atomicAdd(&g_scr[8 + 3*ndB + 1], gyB);
        atomicAdd(&g_scr[8 + 3*ndB + 2], gzB);
        atomicAdd(&g_scr[8 + 3*nsB + 0], -gxB);
        atomicAdd(&g_scr[8 + 3*nsB + 1], -gyB);
        atomicAdd(&g_scr[8 + 3*nsB + 2], -gzB);

        // stress raw: S += bond (outer) f, f = -g   (finalize applies -EV2GPA/vol)
        {
            const float fx = -gxA, fy = -gyA, fz = -gzA;
            float* ss = &sm[OFF_SS + gA * 9];
            atomicAdd(&ss[0], bxA*fx); atomicAdd(&ss[1], bxA*fy); atomicAdd(&ss[2], bxA*fz);
            atomicAdd(&ss[3], byA*fx); atomicAdd(&ss[4], byA*fy); atomicAdd(&ss[5], byA*fz);
            atomicAdd(&ss[6], bzA*fx); atomicAdd(&ss[7], bzA*fy); atomicAdd(&ss[8], bzA*fz);
        }
        {
            const float fx = -gxB, fy = -gyB, fz = -gzB;
            float* ss = &sm[OFF_SS + gB * 9];
            atomicAdd(&ss[0], bxB*fx); atomicAdd(&ss[1], bxB*fy); atomicAdd(&ss[2], bxB*fz);
            atomicAdd(&ss[3], byB*fx); atomicAdd(&ss[4], byB*fy); atomicAdd(&ss[5], byB*fz);
            atomicAdd(&ss[6], bzB*fx); atomicAdd(&ss[7], bzB*fy); atomicAdd(&ss[8], bzB*fz);
        }
        atomicAdd(&sm[OFF_SE + gA], eEA);
        atomicAdd(&sm[OFF_SE + gB], eB_energy);
    }

    __syncthreads();
    if (tid < NG)     atomicAdd(&g_scr[tid], sm[OFF_SE + tid]);
    if (tid < NG * 9) atomicAdd(&g_scr[8 + 3 * N + tid], sm[OFF_SS + tid]);
}

// Writes EVERY element of out (out is poisoned), and re-zeros scratch for graph replay.
__global__ void finalize2(float* __restrict__ out, const float* __restrict__ volume,
                          int N, int out_size) {
    int i = blockIdx.x * blockDim.x + threadIdx.x;
    const int nf = 3 * N;
    if (i < 8) {
        out[i] = g_scr[i];
        g_scr[i] = 0.0f;
    } else if (i < 8 + nf) {
        out[i] = -g_scr[i];                         // forces = -gpos
        g_scr[i] = 0.0f;
    } else if (i < 8 + nf + 72) {
        int s = i - 8 - nf;
        int g = s / 9;
        float vol0 = volume[g * (N / NG)];
        out[i] = (-EV2GPA) * g_scr[i] / vol0;       // scaled stress
        g_scr[i] = 0.0f;
    } else if (i < out_size) {
        out[i] = 0.0f;                              // hessian
    }
}

extern "C" void kernel_launch(void* const* d_in, const int* in_sizes, int n_in,
                              void* d_out, int out_size) {
    const float* pos     = (const float*)d_in[0];
    const float* bv      = (const float*)d_in[1];
    const int*   src     = (const int*)  d_in[2];
    const int*   dst     = (const int*)  d_in[3];
    const int*   eg      = (const int*)  d_in[4];
    const float* volume  = (const float*)d_in[5];
    const float* centers = (const float*)d_in[6];
    const float* W1      = (const float*)d_in[7];
    const float* b1      = (const float*)d_in[8];
    const float* W2      = (const float*)d_in[9];
    const float* b2      = (const float*)d_in[10];
    const float* W3      = (const float*)d_in[11];
    const float* b3      = (const float*)d_in[12];
    float* out = (float*)d_out;

    const int N = in_sizes[0] / 3;
    const int E = in_sizes[1] / 3;

    constexpr size_t smem_bytes = (size_t)SMEM_FLOATS * sizeof(float);  // ~222.4 KB
    cudaFuncSetAttribute(fused_edge_kernel,
                         cudaFuncAttributeMaxDynamicSharedMemorySize, (int)smem_bytes);

    // scratch starts zero (static init on first launch; finalize2 re-zeros each replay)
    fused_edge_kernel<<<296, TPB, smem_bytes>>>(pos, bv, src, dst, eg,
                                                W1, b1, W2, b2, W3, b3, centers,
                                                E, N);
    finalize2<<<(out_size + 255) / 256, 256>>>(out, volume, N, out_size);
}

// round 7
// speedup vs baseline: 15.5317x; 13.8260x over previous
#include <cuda_runtime.h>
#include <math.h>

#define RBF_K 32
#define HID   64
#define NG    8
#define NMAX  49152
#define EV2GPA 160.21766208f

#define TBL_N    16384
#define TBL_DMAX 16.0f
#define TBL_INVH ((float)TBL_N / TBL_DMAX)

typedef unsigned long long ull;

// persistent device scratch (static — no runtime allocation)
__device__ float  g_scr[8 + 3 * NMAX + 72];   // [0:8) energy, [8:8+3N) gpos, then raw stress
__device__ float2 g_pts[TBL_N + 1];           // (e, dd) samples
__device__ float4 g_table[TBL_N];             // (e_i, dd_i, e_{i+1}-e_i, dd_{i+1}-dd_i)

__device__ __forceinline__ ull pack2(float lo, float hi) {
    ull r; asm("mov.b64 %0, {%1, %2};" : "=l"(r) : "f"(lo), "f"(hi)); return r;
}
__device__ __forceinline__ void unpack2(ull v, float& lo, float& hi) {
    asm("mov.b64 {%0, %1}, %2;" : "=f"(lo), "=f"(hi) : "l"(v));
}
__device__ __forceinline__ ull fma2(ull a, ull b, ull c) {
    ull d; asm("fma.rn.f32x2 %0, %1, %2, %3;" : "=l"(d) : "l"(a), "l"(b), "l"(c)); return d;
}
__device__ __forceinline__ float red4(ull a0, ull a1) {
    float x0, x1, x2, x3;
    unpack2(a0, x0, x1); unpack2(a1, x2, x3);
    return (x0 + x2) + (x1 + x3);
}
__device__ __forceinline__ float fsigmoid(float z) {
    return __fdividef(1.0f, 1.0f + __expf(-z));
}

// ============================================================================
// Kernel 1: evaluate the scalar function  e(d), dd(d) = de/dd  at grid points
// ============================================================================
#define BTPB 128
// dynamic smem layout (floats)
#define B_W1T 0                       // [HID][RBF_K] transposed
#define B_W2  (B_W1T + HID*RBF_K)     // [HID][HID]
#define B_B1  (B_W2 + HID*HID)
#define B_B2  (B_B1 + HID)
#define B_W3  (B_B2 + HID)
#define B_CT  (B_W3 + HID)
#define B_T   (B_CT + RBF_K)          // [HID][BTPB] t staging
#define B_SMF (B_T + HID*BTPB)

__global__ __launch_bounds__(BTPB, 1)
void build_pts_kernel(const float* __restrict__ W1, const float* __restrict__ b1,
                      const float* __restrict__ W2, const float* __restrict__ b2,
                      const float* __restrict__ W3, const float* __restrict__ b3,
                      const float* __restrict__ centers)
{
    extern __shared__ float sm[];
    const int tid = threadIdx.x;
    for (int i = tid; i < RBF_K * HID; i += BTPB) {
        int k = i / HID, j = i % HID;
        sm[B_W1T + j * RBF_K + k] = W1[i];
    }
    for (int i = tid; i < HID * HID; i += BTPB) sm[B_W2 + i] = W2[i];
    if (tid < HID) {
        sm[B_B1 + tid] = b1[tid];
        sm[B_B2 + tid] = b2[tid];
        sm[B_W3 + tid] = W3[tid];
    }
    if (tid < RBF_K) sm[B_CT + tid] = centers[tid];
    __syncthreads();

    const int idx = blockIdx.x * BTPB + tid;
    if (idx > TBL_N) return;
    const float d = (float)idx * (TBL_DMAX / (float)TBL_N);
    float* __restrict__ st = &sm[B_T];

    // rbf and d(rbf)/d(dist) = -2(d-c)*rbf, packed
    ull rp[RBF_K / 2], dp[RBF_K / 2];
    {
        const float4* ct4 = reinterpret_cast<const float4*>(&sm[B_CT]);
        #pragma unroll
        for (int k4 = 0; k4 < RBF_K / 4; k4++) {
            float4 c = ct4[k4];
            float t0 = d - c.x, t1 = d - c.y, t2 = d - c.z, t3 = d - c.w;
            float r0 = __expf(-t0*t0), r1 = __expf(-t1*t1);
            float r2 = __expf(-t2*t2), r3 = __expf(-t3*t3);
            rp[2*k4+0] = pack2(r0, r1);               rp[2*k4+1] = pack2(r2, r3);
            dp[2*k4+0] = pack2(-2.f*t0*r0, -2.f*t1*r1);
            dp[2*k4+1] = pack2(-2.f*t2*r2, -2.f*t3*r3);
        }
    }

    // layer1 (+ u-trick) streamed into layer2 accumulator
    ull z2p[HID / 2];
    {
        const ulonglong2* b2p = reinterpret_cast<const ulonglong2*>(&sm[B_B2]);
        #pragma unroll
        for (int i = 0; i < HID / 4; i++) {
            ulonglong2 b = b2p[i];
            z2p[2*i+0] = b.x; z2p[2*i+1] = b.y;
        }
    }
    #pragma unroll 1
    for (int j = 0; j < HID; j++) {
        const ulonglong2* w1p = reinterpret_cast<const ulonglong2*>(&sm[B_W1T + j * RBF_K]);
        ull z0 = 0, z1a = 0, u0 = 0, u1 = 0;
        #pragma unroll
        for (int i = 0; i < RBF_K / 4; i++) {
            ulonglong2 w = w1p[i];
            z0  = fma2(rp[2*i+0], w.x, z0);   z1a = fma2(rp[2*i+1], w.y, z1a);
            u0  = fma2(dp[2*i+0], w.x, u0);   u1  = fma2(dp[2*i+1], w.y, u1);
        }
        const float z1 = red4(z0, z1a) + sm[B_B1 + j];
        const float u  = red4(u0, u1);
        const float sg = fsigmoid(z1);
        const float h  = z1 * sg;
        st[j * BTPB + tid] = (sg * (1.0f + z1 * (1.0f - sg))) * u;   // silu'(z1)*u

        const ull h2 = pack2(h, h);
        const ulonglong2* w2p = reinterpret_cast<const ulonglong2*>(&sm[B_W2 + j * HID]);
        #pragma unroll
        for (int i = 0; i < HID / 4; i++) {
            ulonglong2 w = w2p[i];
            z2p[2*i+0] = fma2(h2, w.x, z2p[2*i+0]);
            z2p[2*i+1] = fma2(h2, w.y, z2p[2*i+1]);
        }
    }

    // output layer + dz2 in place (upstream grad = 1)
    float ee = b3[0];
    {
        const float2* w3f = reinterpret_cast<const float2*>(&sm[B_W3]);
        #pragma unroll
        for (int p = 0; p < HID / 2; p++) {
            float2 w3 = w3f[p];
            float zl, zh;
            unpack2(z2p[p], zl, zh);
            float sgl = fsigmoid(zl), sgh = fsigmoid(zh);
            ee += zl * sgl * w3.x + zh * sgh * w3.y;
            z2p[p] = pack2(w3.x * (sgl * (1.0f + zl * (1.0f - sgl))),
                           w3.y * (sgh * (1.0f + zh * (1.0f - sgh))));
        }
    }

    // backward: dd = sum_j (sum_m dz2_m W2[j,m]) * t_j
    float dd = 0.0f;
    #pragma unroll 1
    for (int j = 0; j < HID; j++) {
        const ulonglong2* w2p = reinterpret_cast<const ulonglong2*>(&sm[B_W2 + j * HID]);
        ull a0 = 0, a1 = 0;
        #pragma unroll
        for (int i = 0; i < HID / 4; i++) {
            ulonglong2 w = w2p[i];
            a0 = fma2(z2p[2*i+0], w.x, a0);
            a1 = fma2(z2p[2*i+1], w.y, a1);
        }
        dd += red4(a0, a1) * st[j * BTPB + tid];
    }

    g_pts[idx] = make_float2(ee, dd);
}

// ============================================================================
// Kernel 2: pack adjacent samples into interp-friendly float4
// ============================================================================
__global__ void pack_table_kernel() {
    int i = blockIdx.x * blockDim.x + threadIdx.x;
    if (i < TBL_N) {
        float2 a = g_pts[i], b = g_pts[i + 1];
        g_table[i] = make_float4(a.x, a.y, b.x - a.x, b.y - a.y);
    }
}

// ============================================================================
// Kernel 3: per-edge — dist, table interp, force REDs, energy/stress reduce
// ============================================================================
#define ETPB 256
#define EPT  4     // edges per thread; block tile = 1024 (divides 98304 graph blocks)

__global__ __launch_bounds__(ETPB)
void edge_kernel(const float* __restrict__ pos, const float* __restrict__ bv,
                 const int* __restrict__ src, const int* __restrict__ dst,
                 const int* __restrict__ eg, int E, int N)
{
    __shared__ float se[NG];
    __shared__ float ss[NG * 9];
    const int tid = threadIdx.x;
    if (tid < NG)     se[tid] = 0.0f;
    if (tid < NG * 9) ss[tid] = 0.0f;
    __syncthreads();

    const int lane = tid & 31;
    const int warp_base = blockIdx.x * (ETPB * EPT) + (tid >> 5) * (32 * EPT);

    float acc[10];
    #pragma unroll
    for (int q = 0; q < 10; q++) acc[q] = 0.0f;
    int g0 = -1;

    #pragma unroll
    for (int k = 0; k < EPT; k++) {
        const int e = warp_base + k * 32 + lane;
        if (e >= E) break;
        const int ns = src[e], nd = dst[e], g = eg[e];
        const float bx = bv[3*e+0], by = bv[3*e+1], bz = bv[3*e+2];
        const float dx = bx + pos[3*nd+0] - pos[3*ns+0];
        const float dy = by + pos[3*nd+1] - pos[3*ns+1];
        const float dz = bz + pos[3*nd+2] - pos[3*ns+2];
        const float dist = sqrtf(dx*dx + dy*dy + dz*dz + 1e-12f);

        // table interp (clamped: beyond DMAX the function is exactly constant in fp32)
        float s = fminf(dist * TBL_INVH, (float)TBL_N - 0.001f);
        const int   ti = (int)s;
        const float fr = s - (float)ti;
        const float4 tb = g_table[ti];
        const float ee = tb.x + fr * tb.z;
        const float dd = tb.y + fr * tb.w;

        const float sc = __fdividef(dd, dist);
        const float gx = sc * dx, gy = sc * dy, gz = sc * dz;  // gpos contribution

        atomicAdd(&g_scr[8 + 3*nd + 0],  gx);
        atomicAdd(&g_scr[8 + 3*nd + 1],  gy);
        atomicAdd(&g_scr[8 + 3*nd + 2],  gz);
        atomicAdd(&g_scr[8 + 3*ns + 0], -gx);
        atomicAdd(&g_scr[8 + 3*ns + 1], -gy);
        atomicAdd(&g_scr[8 + 3*ns + 2], -gz);

        const float fx = -gx, fy = -gy, fz = -gz;   // f_ij
        if (g0 < 0) g0 = g;
        if (g == g0) {
            acc[0] += ee;
            acc[1] += bx*fx; acc[2] += bx*fy; acc[3] += bx*fz;
            acc[4] += by*fx; acc[5] += by*fy; acc[6] += by*fz;
            acc[7] += bz*fx; acc[8] += bz*fy; acc[9] += bz*fz;
        } else {   // robustness fallback (never taken for this input layout)
            atomicAdd(&se[g], ee);
            atomicAdd(&ss[g*9+0], bx*fx); atomicAdd(&ss[g*9+1], bx*fy); atomicAdd(&ss[g*9+2], bx*fz);
            atomicAdd(&ss[g*9+3], by*fx); atomicAdd(&ss[g*9+4], by*fy); atomicAdd(&ss[g*9+5], by*fz);
            atomicAdd(&ss[g*9+6], bz*fx); atomicAdd(&ss[g*9+7], bz*fy); atomicAdd(&ss[g*9+8], bz*fz);
        }
    }

    // warp-level reduce iff the whole warp shares one graph
    const unsigned mm = __match_any_sync(0xFFFFFFFFu, g0);
    if (mm == 0xFFFFFFFFu) {
        #pragma unroll
        for (int off = 16; off; off >>= 1) {
            #pragma unroll
            for (int q = 0; q < 10; q++)
                acc[q] += __shfl_xor_sync(0xFFFFFFFFu, acc[q], off);
        }
        if (lane == 0 && g0 >= 0) {
            atomicAdd(&se[g0], acc[0]);
            #pragma unroll
            for (int q = 0; q < 9; q++) atomicAdd(&ss[g0*9 + q], acc[1 + q]);
        }
    } else {
        if (g0 >= 0) {
            atomicAdd(&se[g0], acc[0]);
            #pragma unroll
            for (int q = 0; q < 9; q++) atomicAdd(&ss[g0*9 + q], acc[1 + q]);
        }
    }

    __syncthreads();
    if (tid < NG)     atomicAdd(&g_scr[tid], se[tid]);
    if (tid < NG * 9) atomicAdd(&g_scr[8 + 3*N + tid], ss[tid]);
}

// ============================================================================
// Kernel 4: write every out element; re-zero scratch for graph replay
// ============================================================================
__global__ void finalize2(float* __restrict__ out, const float* __restrict__ volume,
                          int N, int out_size) {
    int i = blockIdx.x * blockDim.x + threadIdx.x;
    const int nf = 3 * N;
    if (i < 8) {
        out[i] = g_scr[i];
        g_scr[i] = 0.0f;
    } else if (i < 8 + nf) {
        out[i] = -g_scr[i];                        // forces = -gpos
        g_scr[i] = 0.0f;
    } else if (i < 8 + nf + 72) {
        int s = i - 8 - nf;
        int g = s / 9;
        float vol0 = volume[g * (N / NG)];
        out[i] = (-EV2GPA) * g_scr[i] / vol0;      // scaled stress
        g_scr[i] = 0.0f;
    } else if (i < out_size) {
        out[i] = 0.0f;                             // hessian
    }
}

extern "C" void kernel_launch(void* const* d_in, const int* in_sizes, int n_in,
                              void* d_out, int out_size) {
    const float* pos     = (const float*)d_in[0];
    const float* bv      = (const float*)d_in[1];
    const int*   src     = (const int*)  d_in[2];
    const int*   dst     = (const int*)  d_in[3];
    const int*   eg      = (const int*)  d_in[4];
    const float* volume  = (const float*)d_in[5];
    const float* centers = (const float*)d_in[6];
    const float* W1      = (const float*)d_in[7];
    const float* b1      = (const float*)d_in[8];
    const float* W2      = (const float*)d_in[9];
    const float* b2      = (const float*)d_in[10];
    const float* W3      = (const float*)d_in[11];
    const float* b3      = (const float*)d_in[12];
    float* out = (float*)d_out;

    const int N = in_sizes[0] / 3;
    const int E = in_sizes[1] / 3;

    constexpr size_t bsm = (size_t)B_SMF * sizeof(float);   // ~58 KB
    cudaFuncSetAttribute(build_pts_kernel,
                         cudaFuncAttributeMaxDynamicSharedMemorySize, (int)bsm);

    build_pts_kernel<<<(TBL_N + BTPB) / BTPB, BTPB, bsm>>>(W1, b1, W2, b2, W3, b3, centers);
    pack_table_kernel<<<(TBL_N + 255) / 256, 256>>>();
    edge_kernel<<<(E + ETPB * EPT - 1) / (ETPB * EPT), ETPB>>>(pos, bv, src, dst, eg, E, N);
    finalize2<<<(out_size + 255) / 256, 256>>>(out, volume, N, out_size);
}